// round 6
// baseline (speedup 1.0000x reference)
#include <cuda_runtime.h>
#include <cstdint>

// Problem constants
#define B_      16
#define C_      64
#define HW_     65536      // 256*256

// Radix sort: 4 stable LSD passes of 8 bits over the 32-bit ordered-float
// value (high half of a u64 key). Low 16 bits carry the original spatial
// index; stability => jnp argsort tie order. Channel in separate u8 array.
#define THREADS 256
#define NW      8
#define IPT     4
#define BSIZE   1024               // THREADS * IPT
#define NBLK    64                 // HW_ / BSIZE
#define GRID    (B_ * NBLK)        // 1024 scatter blocks
#define HISTSZ  (B_ * 256 * NBLK)  // 262144 entries

__device__ __align__(16) unsigned long long g_kv0[B_ * HW_];
__device__ __align__(16) unsigned long long g_kv1[B_ * HW_];
__device__ __align__(16) unsigned char      g_c8 [B_ * HW_];
__device__ __align__(16) unsigned int       g_histA[HISTSZ];
__device__ __align__(16) unsigned int       g_histB[HISTSZ];

__device__ __forceinline__ unsigned int f2ord(float f) {
    unsigned int u = __float_as_uint(f);
    return (u & 0x80000000u) ? ~u : (u | 0x80000000u);
}

// -------------------------------------------------------------------------
// Kernel 1: channel max + argmax (first occurrence), emit u64 keys.
// Each thread handles 8 spatial positions as two float4 streams (2x MLP).
// grid = 512 x 256.
// -------------------------------------------------------------------------
__global__ void compute_keys_kernel(const float* __restrict__ x) {
    int gid   = blockIdx.x * 256 + threadIdx.x;   // 0 .. 131071
    int batch = gid >> 13;                        // 8192 pairs per batch
    int p     = gid & 8191;
    int q0 = p, q1 = p + 8192;

    const float4* xb = reinterpret_cast<const float4*>(x)
                       + (size_t)batch * (C_ * (HW_ / 4));

    float4 bA = xb[q0];
    float4 bB = xb[q1];
    int a0 = 0, a1 = 0, a2 = 0, a3 = 0;
    int b0 = 0, b1 = 0, b2 = 0, b3 = 0;
    #pragma unroll
    for (int c = 1; c < C_; ++c) {
        float4 vA = xb[(size_t)c * (HW_ / 4) + q0];
        float4 vB = xb[(size_t)c * (HW_ / 4) + q1];
        if (vA.x > bA.x) { bA.x = vA.x; a0 = c; }
        if (vA.y > bA.y) { bA.y = vA.y; a1 = c; }
        if (vA.z > bA.z) { bA.z = vA.z; a2 = c; }
        if (vA.w > bA.w) { bA.w = vA.w; a3 = c; }
        if (vB.x > bB.x) { bB.x = vB.x; b0 = c; }
        if (vB.y > bB.y) { bB.y = vB.y; b1 = c; }
        if (vB.z > bB.z) { bB.z = vB.z; b2 = c; }
        if (vB.w > bB.w) { bB.w = vB.w; b3 = c; }
    }

    size_t ob = (size_t)batch * HW_;
    unsigned int s0 = (unsigned int)q0 * 4u;
    unsigned int s1 = (unsigned int)q1 * 4u;

    ulonglong2 k01, k23;
    k01.x = ((unsigned long long)f2ord(bA.x) << 32) | (s0 + 0u);
    k01.y = ((unsigned long long)f2ord(bA.y) << 32) | (s0 + 1u);
    k23.x = ((unsigned long long)f2ord(bA.z) << 32) | (s0 + 2u);
    k23.y = ((unsigned long long)f2ord(bA.w) << 32) | (s0 + 3u);
    *reinterpret_cast<ulonglong2*>(g_kv0 + ob + s0)     = k01;
    *reinterpret_cast<ulonglong2*>(g_kv0 + ob + s0 + 2) = k23;
    k01.x = ((unsigned long long)f2ord(bB.x) << 32) | (s1 + 0u);
    k01.y = ((unsigned long long)f2ord(bB.y) << 32) | (s1 + 1u);
    k23.x = ((unsigned long long)f2ord(bB.z) << 32) | (s1 + 2u);
    k23.y = ((unsigned long long)f2ord(bB.w) << 32) | (s1 + 3u);
    *reinterpret_cast<ulonglong2*>(g_kv0 + ob + s1)     = k01;
    *reinterpret_cast<ulonglong2*>(g_kv0 + ob + s1 + 2) = k23;

    *reinterpret_cast<uchar4*>(g_c8 + ob + s0) =
        make_uchar4((unsigned char)a0, (unsigned char)a1,
                    (unsigned char)a2, (unsigned char)a3);
    *reinterpret_cast<uchar4*>(g_c8 + ob + s1) =
        make_uchar4((unsigned char)b0, (unsigned char)b1,
                    (unsigned char)b2, (unsigned char)b3);
}

// -------------------------------------------------------------------------
// Kernel 2: pass-1 per-scatter-block histogram (digit = bits [32,40)).
// Also zeroes g_histB. grid = 1024 x 256; 4 kv per thread via ulonglong2.
// -------------------------------------------------------------------------
__global__ void hist1_kernel() {
    __shared__ unsigned int h[256];
    int tid = threadIdx.x;
    h[tid] = 0;
    __syncthreads();

    size_t base = (size_t)blockIdx.x * BSIZE;
    ulonglong2 v0 = *reinterpret_cast<const ulonglong2*>(g_kv0 + base + tid * 2);
    ulonglong2 v1 = *reinterpret_cast<const ulonglong2*>(g_kv0 + base + 512 + tid * 2);
    atomicAdd(&h[(unsigned)(v0.x >> 32) & 255u], 1u);
    atomicAdd(&h[(unsigned)(v0.y >> 32) & 255u], 1u);
    atomicAdd(&h[(unsigned)(v1.x >> 32) & 255u], 1u);
    atomicAdd(&h[(unsigned)(v1.y >> 32) & 255u], 1u);
    __syncthreads();

    int batch = blockIdx.x >> 6, local = blockIdx.x & 63;
    size_t hidx = ((size_t)batch * 256 + tid) * NBLK + local;
    g_histA[hidx] = h[tid];
    g_histB[hidx] = 0u;
}

// -------------------------------------------------------------------------
// Kernel 3: per-batch exclusive scan of 16384 hist entries (bin-major,
// block-minor). grid = 16 x 1024. Optionally zeroes the other hist buffer.
// -------------------------------------------------------------------------
__global__ void scan_kernel(int which, int zero_other) {
    __shared__ unsigned int warp_sums[32];
    unsigned int* hist = (which ? g_histB : g_histA) + (size_t)blockIdx.x * 16384;
    int tid = threadIdx.x;
    int lane = tid & 31, w = tid >> 5;

    unsigned int v[16];
    unsigned int sum = 0;
    #pragma unroll
    for (int j = 0; j < 16; ++j) { v[j] = hist[tid * 16 + j]; sum += v[j]; }

    unsigned int inc = sum;
    #pragma unroll
    for (int o = 1; o < 32; o <<= 1) {
        unsigned int t = __shfl_up_sync(0xffffffffu, inc, o);
        if (lane >= o) inc += t;
    }
    if (lane == 31) warp_sums[w] = inc;
    __syncthreads();
    if (w == 0) {
        unsigned int ws = warp_sums[lane];
        #pragma unroll
        for (int o = 1; o < 32; o <<= 1) {
            unsigned int t = __shfl_up_sync(0xffffffffu, ws, o);
            if (lane >= o) ws += t;
        }
        warp_sums[lane] = ws;
    }
    __syncthreads();

    unsigned int excl = inc - sum + (w > 0 ? warp_sums[w - 1] : 0u);
    #pragma unroll
    for (int j = 0; j < 16; ++j) { hist[tid * 16 + j] = excl; excl += v[j]; }

    if (zero_other) {
        unsigned int* o = (which ? g_histA : g_histB) + (size_t)blockIdx.x * 16384;
        #pragma unroll
        for (int j = 0; j < 16; ++j) o[tid * 16 + j] = 0u;
    }
}

// -------------------------------------------------------------------------
// Kernel 4: stable scatter, u64 keys, leader-only rank RMW, smem exchange.
// WHICH=0: kv0->kv1, histA cur, histB next. WHICH=1: the reverse.
// grid = 1024 x 256.
// -------------------------------------------------------------------------
template <int SHIFT, int WHICH, bool LAST>
__global__ void scatter_kernel(float4* __restrict__ outv) {
    __shared__ unsigned int       wh[NW][256];
    __shared__ unsigned long long s_kv[BSIZE];
    __shared__ unsigned int       dstart[256];
    __shared__ unsigned int       gbase[256];
    __shared__ unsigned int       sw[NW];

    const unsigned long long* __restrict__ in_kv    = WHICH ? g_kv1 : g_kv0;
    unsigned long long*       __restrict__ out_kv   = WHICH ? g_kv0 : g_kv1;
    const unsigned int*       __restrict__ cur_hist = WHICH ? g_histB : g_histA;
    unsigned int*             __restrict__ next_hist= WHICH ? g_histA : g_histB;

    int tid = threadIdx.x;
    int w = tid >> 5, lane = tid & 31;
    for (int j = tid; j < NW * 256; j += THREADS)
        (&wh[0][0])[j] = 0;
    __syncthreads();

    int blk = blockIdx.x, batch = blk >> 6, local = blk & 63;
    size_t base = (size_t)blk * BSIZE + (size_t)w * (32 * IPT);

    unsigned long long kv[IPT];
    unsigned short rank[IPT];

    #pragma unroll
    for (int i = 0; i < IPT; ++i) {
        kv[i] = in_kv[base + i * 32 + lane];
        unsigned int d = (unsigned)(kv[i] >> (32 + SHIFT)) & 255u;
        unsigned int mask = __match_any_sync(0xffffffffu, d);
        int leader = __ffs(mask) - 1;
        unsigned int r = __popc(mask & ((1u << lane) - 1u));
        unsigned int prev = 0;
        if (r == 0) {                       // leader does the counter RMW
            prev = wh[w][d];
            wh[w][d] = prev + __popc(mask);
        }
        prev = __shfl_sync(0xffffffffu, prev, leader);
        rank[i] = (unsigned short)(prev + r);
        __syncwarp();                       // order RMW vs next item's read
    }
    __syncthreads();

    // Per-bin cross-warp exclusive scan (bin = tid); running = bin total.
    unsigned int running = 0;
    #pragma unroll
    for (int q = 0; q < NW; ++q) {
        unsigned int t = wh[q][tid];
        wh[q][tid] = running;
        running += t;
    }

    // Block-wide exclusive scan over the 256 bin totals.
    unsigned int inc = running;
    #pragma unroll
    for (int o = 1; o < 32; o <<= 1) {
        unsigned int t = __shfl_up_sync(0xffffffffu, inc, o);
        if (lane >= o) inc += t;
    }
    if (lane == 31) sw[w] = inc;
    __syncthreads();
    if (tid == 0) {
        unsigned int r = 0;
        #pragma unroll
        for (int q = 0; q < NW; ++q) { unsigned int t = sw[q]; sw[q] = r; r += t; }
    }
    __syncthreads();
    unsigned int excl = inc - running + sw[w];
    dstart[tid] = excl;
    gbase[tid]  = cur_hist[((size_t)batch * 256 + tid) * NBLK + local] - excl;
    __syncthreads();

    // Exchange into block-digit-sorted order (single u64 STS per item).
    #pragma unroll
    for (int i = 0; i < IPT; ++i) {
        unsigned int d = (unsigned)(kv[i] >> (32 + SHIFT)) & 255u;
        unsigned int p = dstart[d] + wh[w][d] + (unsigned int)rank[i];
        s_kv[p] = kv[i];
    }
    __syncthreads();

    // Coalesced write-out; global pos = gbase[d] + p.
    size_t obase = (size_t)batch * HW_;
    #pragma unroll
    for (int j = 0; j < IPT; ++j) {
        unsigned int p = (unsigned int)tid + j * THREADS;
        unsigned long long k = s_kv[p];
        unsigned int d = (unsigned)(k >> (32 + SHIFT)) & 255u;
        unsigned int pos = gbase[d] + p;
        if (!LAST) {
            out_kv[obase + pos] = k;
            unsigned int d2 = (unsigned)(k >> (40 + SHIFT)) & 255u;
            atomicAdd(&next_hist[((size_t)batch * 256 + d2) * NBLK + (pos >> 10)], 1u);
        } else {
            unsigned int hi = (unsigned int)(k >> 32);
            unsigned int u  = (hi & 0x80000000u) ? (hi ^ 0x80000000u) : ~hi;
            unsigned int s  = (unsigned int)k & 0xFFFFu;
            unsigned int c  = (unsigned int)g_c8[obase + s];
            float4 o;
            o.x = __uint_as_float(u);
            o.y = (float)(c * (unsigned)HW_ + s);   // < 2^22, exact in f32
            o.z = (float)(s >> 8);                  // row (W=256)
            o.w = (float)(s & 255u);                // col
            outv[obase + pos] = o;
        }
    }
}

// -------------------------------------------------------------------------
extern "C" void kernel_launch(void* const* d_in, const int* in_sizes, int n_in,
                              void* d_out, int out_size) {
    const float* x = (const float*)d_in[0];
    float4* out = (float4*)d_out;

    compute_keys_kernel<<<512, 256>>>(x);
    hist1_kernel<<<GRID, THREADS>>>();                     // hist1 -> A, zero B

    scan_kernel<<<16, 1024>>>(0, 0);                       // scan A
    scatter_kernel<0, 0, false><<<GRID, THREADS>>>(nullptr);   // kv0->kv1, hist2->B

    scan_kernel<<<16, 1024>>>(1, 1);                       // scan B, zero A
    scatter_kernel<8, 1, false><<<GRID, THREADS>>>(nullptr);   // kv1->kv0, hist3->A

    scan_kernel<<<16, 1024>>>(0, 1);                       // scan A, zero B
    scatter_kernel<16, 0, false><<<GRID, THREADS>>>(nullptr);  // kv0->kv1, hist4->B

    scan_kernel<<<16, 1024>>>(1, 0);                       // scan B
    scatter_kernel<24, 1, true><<<GRID, THREADS>>>(out);       // kv1->d_out
}

// round 7
// speedup vs baseline: 1.1322x; 1.1322x over previous
#include <cuda_runtime.h>
#include <cstdint>

// Problem constants
#define B_      16
#define C_      64
#define HW_     65536      // 256*256

// Radix sort: 4 stable LSD passes of 8 bits over the 32-bit ordered-float
// value (high half of a u64 key). Low bits: channel<<16 | spatial(16).
// Keys generated in spatial order; stability => jnp argsort tie order.
#define THREADS 256
#define NW      8
#define IPT     4
#define BSIZE   1024               // THREADS * IPT
#define NBLK    64                 // HW_ / BSIZE
#define GRID    (B_ * NBLK)        // 1024 scatter blocks
#define HISTSZ  (B_ * 256 * NBLK)  // 262144 entries

__device__ __align__(16) unsigned long long g_kv0[B_ * HW_];
__device__ __align__(16) unsigned long long g_kv1[B_ * HW_];
__device__ __align__(16) unsigned int       g_histA[HISTSZ];
__device__ __align__(16) unsigned int       g_histB[HISTSZ];

__device__ __forceinline__ unsigned int f2ord(float f) {
    unsigned int u = __float_as_uint(f);
    return (u & 0x80000000u) ? ~u : (u | 0x80000000u);
}

// -------------------------------------------------------------------------
// Kernel 1: channel max + argmax (first occurrence), emit u64 keys with
// channel+spatial embedded. grid = 1024 x 256, 4 consecutive positions per
// thread via float4 streaming loads.
// -------------------------------------------------------------------------
__global__ void compute_keys_kernel(const float* __restrict__ x) {
    int gid   = blockIdx.x * 256 + threadIdx.x;
    int batch = gid >> 14;
    int q     = gid & 16383;

    const float4* xb = reinterpret_cast<const float4*>(x)
                       + (size_t)batch * (C_ * (HW_ / 4)) + q;

    float4 best = xb[0];
    int c0 = 0, c1 = 0, c2 = 0, c3 = 0;
    #pragma unroll
    for (int c = 1; c < C_; ++c) {
        float4 v = xb[(size_t)c * (HW_ / 4)];
        if (v.x > best.x) { best.x = v.x; c0 = c; }
        if (v.y > best.y) { best.y = v.y; c1 = c; }
        if (v.z > best.z) { best.z = v.z; c2 = c; }
        if (v.w > best.w) { best.w = v.w; c3 = c; }
    }

    size_t o = (size_t)batch * HW_;
    unsigned int s = (unsigned int)q * 4u;
    ulonglong2 k01, k23;
    k01.x = ((unsigned long long)f2ord(best.x) << 32) | ((unsigned)c0 << 16) | (s + 0u);
    k01.y = ((unsigned long long)f2ord(best.y) << 32) | ((unsigned)c1 << 16) | (s + 1u);
    k23.x = ((unsigned long long)f2ord(best.z) << 32) | ((unsigned)c2 << 16) | (s + 2u);
    k23.y = ((unsigned long long)f2ord(best.w) << 32) | ((unsigned)c3 << 16) | (s + 3u);
    *reinterpret_cast<ulonglong2*>(g_kv0 + o + s)     = k01;
    *reinterpret_cast<ulonglong2*>(g_kv0 + o + s + 2) = k23;
}

// -------------------------------------------------------------------------
// Kernel 2: pass-1 per-scatter-block histogram (digit = bits [32,40)).
// Also zeroes g_histB. grid = 1024 x 256; 4 kv per thread via ulonglong2.
// -------------------------------------------------------------------------
__global__ void hist1_kernel() {
    __shared__ unsigned int h[256];
    int tid = threadIdx.x;
    h[tid] = 0;
    __syncthreads();

    size_t base = (size_t)blockIdx.x * BSIZE;
    ulonglong2 v0 = *reinterpret_cast<const ulonglong2*>(g_kv0 + base + tid * 2);
    ulonglong2 v1 = *reinterpret_cast<const ulonglong2*>(g_kv0 + base + 512 + tid * 2);
    atomicAdd(&h[(unsigned)(v0.x >> 32) & 255u], 1u);
    atomicAdd(&h[(unsigned)(v0.y >> 32) & 255u], 1u);
    atomicAdd(&h[(unsigned)(v1.x >> 32) & 255u], 1u);
    atomicAdd(&h[(unsigned)(v1.y >> 32) & 255u], 1u);
    __syncthreads();

    int batch = blockIdx.x >> 6, local = blockIdx.x & 63;
    size_t hidx = ((size_t)batch * 256 + tid) * NBLK + local;
    g_histA[hidx] = h[tid];
    g_histB[hidx] = 0u;
}

// -------------------------------------------------------------------------
// Kernel 3: per-batch exclusive scan of 16384 hist entries (bin-major,
// block-minor). grid = 16 x 1024. Optionally zeroes the other hist buffer.
// -------------------------------------------------------------------------
__global__ void scan_kernel(int which, int zero_other) {
    __shared__ unsigned int warp_sums[32];
    unsigned int* hist = (which ? g_histB : g_histA) + (size_t)blockIdx.x * 16384;
    int tid = threadIdx.x;
    int lane = tid & 31, w = tid >> 5;

    unsigned int v[16];
    unsigned int sum = 0;
    #pragma unroll
    for (int j = 0; j < 16; ++j) { v[j] = hist[tid * 16 + j]; sum += v[j]; }

    unsigned int inc = sum;
    #pragma unroll
    for (int o = 1; o < 32; o <<= 1) {
        unsigned int t = __shfl_up_sync(0xffffffffu, inc, o);
        if (lane >= o) inc += t;
    }
    if (lane == 31) warp_sums[w] = inc;
    __syncthreads();
    if (w == 0) {
        unsigned int ws = warp_sums[lane];
        #pragma unroll
        for (int o = 1; o < 32; o <<= 1) {
            unsigned int t = __shfl_up_sync(0xffffffffu, ws, o);
            if (lane >= o) ws += t;
        }
        warp_sums[lane] = ws;
    }
    __syncthreads();

    unsigned int excl = inc - sum + (w > 0 ? warp_sums[w - 1] : 0u);
    #pragma unroll
    for (int j = 0; j < 16; ++j) { hist[tid * 16 + j] = excl; excl += v[j]; }

    if (zero_other) {
        unsigned int* o = (which ? g_histA : g_histB) + (size_t)blockIdx.x * 16384;
        #pragma unroll
        for (int j = 0; j < 16; ++j) o[tid * 16 + j] = 0u;
    }
}

// -------------------------------------------------------------------------
// Kernel 4: stable scatter. Ballot-based parallel ranking (no serialized
// smem counter chain, no __syncwarp in the rank loop), smem exchange for
// coalesced writes. WHICH=0: kv0->kv1, histA cur, histB next. grid=1024x256.
// -------------------------------------------------------------------------
template <int SHIFT, int WHICH, bool LAST>
__global__ void __launch_bounds__(THREADS, 4)
scatter_kernel(float4* __restrict__ outv) {
    __shared__ unsigned int       wh[NW][256];
    __shared__ unsigned long long s_kv[BSIZE];
    __shared__ unsigned int       dstart[256];
    __shared__ unsigned int       gbase[256];
    __shared__ unsigned int       sw[NW];

    const unsigned long long* __restrict__ in_kv    = WHICH ? g_kv1 : g_kv0;
    unsigned long long*       __restrict__ out_kv   = WHICH ? g_kv0 : g_kv1;
    const unsigned int*       __restrict__ cur_hist = WHICH ? g_histB : g_histA;
    unsigned int*             __restrict__ next_hist= WHICH ? g_histA : g_histB;

    int tid = threadIdx.x;
    int w = tid >> 5, lane = tid & 31;
    unsigned int lt = (1u << lane) - 1u;
    for (int j = tid; j < NW * 256; j += THREADS)
        (&wh[0][0])[j] = 0;
    __syncthreads();

    int blk = blockIdx.x, batch = blk >> 6, local = blk & 63;
    size_t base = (size_t)blk * BSIZE + (size_t)w * (32 * IPT);

    unsigned long long kv[IPT];
    unsigned int d[IPT];
    unsigned int bal[IPT][8];

    #pragma unroll
    for (int i = 0; i < IPT; ++i) {
        kv[i] = in_kv[base + i * 32 + lane];
        d[i] = (unsigned)(kv[i] >> (32 + SHIFT)) & 255u;
        #pragma unroll
        for (int b = 0; b < 8; ++b)
            bal[i][b] = __ballot_sync(0xffffffffu, (d[i] >> b) & 1u);
    }

    // rank[i] = #equal-digit items earlier in warp order (item-major,
    // lane-minor). m_ij = lanes of item j whose digit == my item-i digit.
    unsigned int rank[IPT];
    #pragma unroll
    for (int i = 0; i < IPT; ++i) {
        unsigned int r = 0;
        #pragma unroll
        for (int j = 0; j <= i; ++j) {
            unsigned int m = 0xffffffffu;
            #pragma unroll
            for (int b = 0; b < 8; ++b)
                m &= bal[j][b] ^ (((d[i] >> b) & 1u) - 1u);
            if (j < i) {
                r += __popc(m);
            } else {
                unsigned int rw = __popc(m & lt);
                r += rw;
                if (rw == 0)                      // item-digit leader publishes
                    atomicAdd(&wh[w][d[i]], __popc(m));
            }
        }
        rank[i] = r;
    }
    __syncthreads();

    // Per-bin cross-warp exclusive scan (bin = tid); running = bin total.
    unsigned int running = 0;
    #pragma unroll
    for (int q = 0; q < NW; ++q) {
        unsigned int t = wh[q][tid];
        wh[q][tid] = running;
        running += t;
    }

    // Block-wide exclusive scan over the 256 bin totals.
    unsigned int inc = running;
    #pragma unroll
    for (int o = 1; o < 32; o <<= 1) {
        unsigned int t = __shfl_up_sync(0xffffffffu, inc, o);
        if (lane >= o) inc += t;
    }
    if (lane == 31) sw[w] = inc;
    __syncthreads();
    if (tid == 0) {
        unsigned int r = 0;
        #pragma unroll
        for (int q = 0; q < NW; ++q) { unsigned int t = sw[q]; sw[q] = r; r += t; }
    }
    __syncthreads();
    unsigned int excl = inc - running + sw[w];
    dstart[tid] = excl;
    gbase[tid]  = cur_hist[((size_t)batch * 256 + tid) * NBLK + local] - excl;
    __syncthreads();

    // Exchange into block-digit-sorted order.
    #pragma unroll
    for (int i = 0; i < IPT; ++i) {
        unsigned int p = dstart[d[i]] + wh[w][d[i]] + rank[i];
        s_kv[p] = kv[i];
    }
    __syncthreads();

    // Coalesced write-out; global pos = gbase[digit] + p.
    size_t obase = (size_t)batch * HW_;
    #pragma unroll
    for (int j = 0; j < IPT; ++j) {
        unsigned int p = (unsigned int)tid + j * THREADS;
        unsigned long long k = s_kv[p];
        unsigned int dd = (unsigned)(k >> (32 + SHIFT)) & 255u;
        unsigned int pos = gbase[dd] + p;
        if (!LAST) {
            out_kv[obase + pos] = k;
            unsigned int d2 = (unsigned)(k >> (40 + SHIFT)) & 255u;
            atomicAdd(&next_hist[((size_t)batch * 256 + d2) * NBLK + (pos >> 10)], 1u);
        } else {
            unsigned int hi = (unsigned int)(k >> 32);
            unsigned int u  = (hi & 0x80000000u) ? (hi ^ 0x80000000u) : ~hi;
            unsigned int lo = (unsigned int)k & 0x3FFFFFu;   // c<<16 | s  == flat idx
            unsigned int s  = lo & 0xFFFFu;
            float4 o;
            o.x = __uint_as_float(u);
            o.y = (float)lo;                      // c*65536 + s, < 2^22, exact
            o.z = (float)(s >> 8);                // row (W=256)
            o.w = (float)(s & 255u);              // col
            outv[obase + pos] = o;
        }
    }
}

// -------------------------------------------------------------------------
extern "C" void kernel_launch(void* const* d_in, const int* in_sizes, int n_in,
                              void* d_out, int out_size) {
    const float* x = (const float*)d_in[0];
    float4* out = (float4*)d_out;

    compute_keys_kernel<<<1024, 256>>>(x);
    hist1_kernel<<<GRID, THREADS>>>();                     // hist1 -> A, zero B

    scan_kernel<<<16, 1024>>>(0, 0);                       // scan A
    scatter_kernel<0, 0, false><<<GRID, THREADS>>>(nullptr);   // kv0->kv1, hist2->B

    scan_kernel<<<16, 1024>>>(1, 1);                       // scan B, zero A
    scatter_kernel<8, 1, false><<<GRID, THREADS>>>(nullptr);   // kv1->kv0, hist3->A

    scan_kernel<<<16, 1024>>>(0, 1);                       // scan A, zero B
    scatter_kernel<16, 0, false><<<GRID, THREADS>>>(nullptr);  // kv0->kv1, hist4->B

    scan_kernel<<<16, 1024>>>(1, 0);                       // scan B
    scatter_kernel<24, 1, true><<<GRID, THREADS>>>(out);       // kv1->d_out
}